// round 1
// baseline (speedup 1.0000x reference)
#include <cuda_runtime.h>

#define BB 16
#define HH 8
#define GG 1024
#define II 256
#define DD 64
#define NEG_INF (-1e30f)

// scratch for q, k, v projections: [b][h][g][d]
__device__ float g_q[BB*HH*GG*DD];
__device__ float g_k[BB*HH*GG*DD];
__device__ float g_v[BB*HH*GG*DD];

// ---------------------------------------------------------------------------
// Projection: C[16384 x 64] per (head, type) = A[16384 x 256] @ W[h][256 x 64]
// Tile: BM=128, BN=64 (full), BK=32. 256 threads, 8x4 microtile (16x16 grid).
// ---------------------------------------------------------------------------
__global__ __launch_bounds__(256) void proj_kernel(
    const float* __restrict__ A,      // [16384, 256] (= h reshaped)
    const float* __restrict__ W,      // [8, 256, 64]
    int which)                        // 0=q, 1=k, 2=v
{
    __shared__ float As[32][132];     // k-major, padded
    __shared__ float Bs[32][64];

    float* outbuf = (which == 0) ? g_q : (which == 1) ? g_k : g_v;

    const int hh = blockIdx.y;
    const int r0 = blockIdx.x * 128;
    const float* Wh = W + hh * II * DD;

    const int tid = threadIdx.x;
    const int tm = tid >> 4;          // 0..15 -> rows tm*8..tm*8+7
    const int tn = tid & 15;          // 0..15 -> cols tn*4..tn*4+3

    float acc[8][4];
#pragma unroll
    for (int i = 0; i < 8; i++)
#pragma unroll
        for (int j = 0; j < 4; j++) acc[i][j] = 0.f;

    for (int k0 = 0; k0 < II; k0 += 32) {
        // A tile 128x32 -> As[k][m] (transposed)
#pragma unroll
        for (int t = 0; t < 4; t++) {
            int id  = tid + t * 256;
            int row = id >> 3;
            int c4  = (id & 7) << 2;
            float4 v = *(const float4*)(A + (r0 + row) * II + k0 + c4);
            As[c4 + 0][row] = v.x;
            As[c4 + 1][row] = v.y;
            As[c4 + 2][row] = v.z;
            As[c4 + 3][row] = v.w;
        }
        // W tile 32x64 natural
#pragma unroll
        for (int t = 0; t < 2; t++) {
            int id  = tid + t * 256;
            int row = id >> 4;
            int c4  = (id & 15) << 2;
            *(float4*)(&Bs[row][c4]) = *(const float4*)(Wh + (k0 + row) * DD + c4);
        }
        __syncthreads();

#pragma unroll 8
        for (int kk = 0; kk < 32; kk++) {
            float a[8], b[4];
            *(float4*)(a)     = *(const float4*)(&As[kk][tm * 8]);
            *(float4*)(a + 4) = *(const float4*)(&As[kk][tm * 8 + 4]);
            *(float4*)(b)     = *(const float4*)(&Bs[kk][tn * 4]);
#pragma unroll
            for (int i = 0; i < 8; i++)
#pragma unroll
                for (int j = 0; j < 4; j++)
                    acc[i][j] += a[i] * b[j];
        }
        __syncthreads();
    }

    // write: row r -> batch b = r>>10, g = r & 1023; out [b][h][g][d]
#pragma unroll
    for (int ii = 0; ii < 8; ii++) {
        int r  = r0 + tm * 8 + ii;
        int b  = r >> 10;
        int g  = r & (GG - 1);
        float4 o4 = make_float4(acc[ii][0], acc[ii][1], acc[ii][2], acc[ii][3]);
        *(float4*)(outbuf + (((b * HH + hh) * GG + g) * DD) + tn * 4) = o4;
    }
}

// ---------------------------------------------------------------------------
// Flash attention: one CTA per (b*h, q-tile of 64). 128 threads.
// SMEM (static, 48KB): Qs[d][64] d-major, KP[64][64] (K d-major, reused as
// P row-major), Vs[64][64] natural. 8x4 microtiles; width-16 shfl reductions.
// ---------------------------------------------------------------------------
__global__ __launch_bounds__(128) void attn_kernel(
    const int* __restrict__ mask,     // [1024,1024], nonzero = disallowed
    float* __restrict__ out)          // [b][h][g][64]
{
    __shared__ float Qs[64 * 64];     // Qs[d*64 + i]
    __shared__ float KP[64 * 64];     // Ks[d*64 + j]  then  Ps[i*64 + j]
    __shared__ float Vs[64 * 64];     // Vs[j*64 + n]

    const int q0 = blockIdx.x * 64;
    const int bh = blockIdx.y;

    const float* qb = g_q + (size_t)bh * GG * DD;
    const float* kb = g_k + (size_t)bh * GG * DD;
    const float* vb = g_v + (size_t)bh * GG * DD;

    const int tid = threadIdx.x;
    const int tm = tid >> 4;          // 0..7  -> i rows tm*8..+7
    const int tn = tid & 15;          // 0..15 -> cols tn*4..+3

    // load Q tile transposed (d-major)
#pragma unroll
    for (int t = 0; t < 8; t++) {
        int id = tid + t * 128;
        int i  = id >> 4;
        int d4 = (id & 15) << 2;
        float4 v = *(const float4*)(qb + (q0 + i) * DD + d4);
        Qs[(d4 + 0) * 64 + i] = v.x;
        Qs[(d4 + 1) * 64 + i] = v.y;
        Qs[(d4 + 2) * 64 + i] = v.z;
        Qs[(d4 + 3) * 64 + i] = v.w;
    }

    float o[8][4];
    float m[8], l[8];
#pragma unroll
    for (int ii = 0; ii < 8; ii++) {
        m[ii] = -3.0e38f;
        l[ii] = 0.f;
#pragma unroll
        for (int jj = 0; jj < 4; jj++) o[ii][jj] = 0.f;
    }
    const float scale = 0.125f;       // 1/sqrt(64)

    for (int k0 = 0; k0 < GG; k0 += 64) {
        __syncthreads();              // prior-iter readers done before refill
        // load K transposed + V natural
#pragma unroll
        for (int t = 0; t < 8; t++) {
            int id = tid + t * 128;
            int j  = id >> 4;
            int d4 = (id & 15) << 2;
            float4 kv = *(const float4*)(kb + (k0 + j) * DD + d4);
            KP[(d4 + 0) * 64 + j] = kv.x;
            KP[(d4 + 1) * 64 + j] = kv.y;
            KP[(d4 + 2) * 64 + j] = kv.z;
            KP[(d4 + 3) * 64 + j] = kv.w;
            *(float4*)(&Vs[j * 64 + d4]) = *(const float4*)(vb + (k0 + j) * DD + d4);
        }
        __syncthreads();

        // S = Q K^T  (accumulate in registers)
        float s[8][4];
#pragma unroll
        for (int ii = 0; ii < 8; ii++)
#pragma unroll
            for (int jj = 0; jj < 4; jj++) s[ii][jj] = 0.f;

#pragma unroll 8
        for (int d = 0; d < 64; d++) {
            float a[8], b[4];
            *(float4*)(a)     = *(const float4*)(&Qs[d * 64 + tm * 8]);
            *(float4*)(a + 4) = *(const float4*)(&Qs[d * 64 + tm * 8 + 4]);
            *(float4*)(b)     = *(const float4*)(&KP[d * 64 + tn * 4]);
#pragma unroll
            for (int ii = 0; ii < 8; ii++)
#pragma unroll
                for (int jj = 0; jj < 4; jj++)
                    s[ii][jj] += a[ii] * b[jj];
        }
        __syncthreads();              // done reading K before P overwrite

        // mask + scale + online softmax (rows owned by 16 tn-lanes each)
#pragma unroll
        for (int ii = 0; ii < 8; ii++) {
            int qi = q0 + tm * 8 + ii;
            int4 mk = *(const int4*)(mask + qi * GG + k0 + tn * 4);
            s[ii][0] = mk.x ? NEG_INF : s[ii][0] * scale;
            s[ii][1] = mk.y ? NEG_INF : s[ii][1] * scale;
            s[ii][2] = mk.z ? NEG_INF : s[ii][2] * scale;
            s[ii][3] = mk.w ? NEG_INF : s[ii][3] * scale;

            float tmax = fmaxf(fmaxf(s[ii][0], s[ii][1]), fmaxf(s[ii][2], s[ii][3]));
#pragma unroll
            for (int off = 8; off; off >>= 1)
                tmax = fmaxf(tmax, __shfl_xor_sync(0xffffffffu, tmax, off, 16));

            float mn    = fmaxf(m[ii], tmax);
            float alpha = __expf(m[ii] - mn);
            m[ii] = mn;

            float rs = 0.f;
#pragma unroll
            for (int jj = 0; jj < 4; jj++) {
                s[ii][jj] = __expf(s[ii][jj] - mn);
                rs += s[ii][jj];
            }
#pragma unroll
            for (int off = 8; off; off >>= 1)
                rs += __shfl_xor_sync(0xffffffffu, rs, off, 16);

            l[ii] = l[ii] * alpha + rs;
#pragma unroll
            for (int jj = 0; jj < 4; jj++) o[ii][jj] *= alpha;

            // stash P row-major into the K buffer
            *(float4*)(&KP[(tm * 8 + ii) * 64 + tn * 4]) =
                make_float4(s[ii][0], s[ii][1], s[ii][2], s[ii][3]);
        }
        __syncthreads();

        // O += P @ V
#pragma unroll 4
        for (int j = 0; j < 64; j++) {
            float b[4];
            *(float4*)(b) = *(const float4*)(&Vs[j * 64 + tn * 4]);
#pragma unroll
            for (int ii = 0; ii < 8; ii++) {
                float a = KP[(tm * 8 + ii) * 64 + j];
#pragma unroll
                for (int jj = 0; jj < 4; jj++)
                    o[ii][jj] += a * b[jj];
            }
        }
    }

    // epilogue: normalize and store
#pragma unroll
    for (int ii = 0; ii < 8; ii++) {
        float inv = 1.f / l[ii];
        float4 o4 = make_float4(o[ii][0] * inv, o[ii][1] * inv,
                                o[ii][2] * inv, o[ii][3] * inv);
        *(float4*)(out + ((size_t)bh * GG + q0 + tm * 8 + ii) * DD + tn * 4) = o4;
    }
}

// ---------------------------------------------------------------------------
extern "C" void kernel_launch(void* const* d_in, const int* in_sizes, int n_in,
                              void* d_out, int out_size)
{
    const float* h    = (const float*)d_in[0];   // [16,1024,256]
    const int*   mask = (const int*)  d_in[1];   // [1024,1024]
    const float* W_Q  = (const float*)d_in[2];   // [8,256,64]
    const float* W_K  = (const float*)d_in[3];
    const float* W_V  = (const float*)d_in[4];
    float* out = (float*)d_out;                  // [16,8,1024,64]

    dim3 pgrid(128, 8);                          // 16384/128 row tiles x 8 heads
    proj_kernel<<<pgrid, 256>>>(h, W_Q, 0);
    proj_kernel<<<pgrid, 256>>>(h, W_K, 1);
    proj_kernel<<<pgrid, 256>>>(h, W_V, 2);

    dim3 agrid(GG / 64, BB * HH);                // 16 q-tiles x 128 (b,h)
    attn_kernel<<<agrid, 128>>>(mask, out);
}

// round 2
// speedup vs baseline: 1.0411x; 1.0411x over previous
#include <cuda_runtime.h>
#include <cstdint>

#define BB 16
#define HH 8
#define GG 1024
#define II 256
#define DD 64
#define NEG_INF (-1e30f)

// scratch for q, k, v projections: [b][h][g][d]
__device__ float g_q[BB*HH*GG*DD];
__device__ float g_k[BB*HH*GG*DD];
__device__ float g_v[BB*HH*GG*DD];

// ---- packed f32x2 helpers (sm_100+) --------------------------------------
__device__ __forceinline__ unsigned long long f2pack(float lo, float hi) {
    unsigned long long r;
    asm("mov.b64 %0, {%1, %2};" : "=l"(r) : "f"(lo), "f"(hi));
    return r;
}
__device__ __forceinline__ void f2unpack(unsigned long long v, float& lo, float& hi) {
    asm("mov.b64 {%0, %1}, %2;" : "=f"(lo), "=f"(hi) : "l"(v));
}
__device__ __forceinline__ void ffma2(unsigned long long& d,
                                      unsigned long long a, unsigned long long b) {
    asm("fma.rn.f32x2 %0, %1, %2, %0;" : "+l"(d) : "l"(a), "l"(b));
}
__device__ __forceinline__ unsigned long long fmul2(unsigned long long a,
                                                    unsigned long long b) {
    unsigned long long r;
    asm("mul.rn.f32x2 %0, %1, %2;" : "=l"(r) : "l"(a), "l"(b));
    return r;
}

// ---------------------------------------------------------------------------
// Projection: C[16384 x 64] per (head, type) = A[16384 x 256] @ W[h][256 x 64]
// Tile: BM=128, BN=64 (full), BK=32. 256 threads, 8x4 microtile, FFMA2 pairs
// along rows (free from k-major As).
// ---------------------------------------------------------------------------
__global__ __launch_bounds__(256) void proj_kernel(
    const float* __restrict__ A,      // [16384, 256]
    const float* __restrict__ W,      // [8, 256, 64]
    int which)
{
    __shared__ float As[32][132];     // k-major, padded (132*4=528B, 16B mult)
    __shared__ float Bs[32][64];

    float* outbuf = (which == 0) ? g_q : (which == 1) ? g_k : g_v;

    const int hh = blockIdx.y;
    const int r0 = blockIdx.x * 128;
    const float* Wh = W + hh * II * DD;

    const int tid = threadIdx.x;
    const int tm = tid >> 4;
    const int tn = tid & 15;

    unsigned long long acc2[4][4];    // [row-pair][col], lo=row 2p, hi=row 2p+1
#pragma unroll
    for (int i = 0; i < 4; i++)
#pragma unroll
        for (int j = 0; j < 4; j++) acc2[i][j] = 0ull;

    for (int k0 = 0; k0 < II; k0 += 32) {
#pragma unroll
        for (int t = 0; t < 4; t++) {
            int id  = tid + t * 256;
            int row = id >> 3;
            int c4  = (id & 7) << 2;
            float4 v = *(const float4*)(A + (r0 + row) * II + k0 + c4);
            As[c4 + 0][row] = v.x;
            As[c4 + 1][row] = v.y;
            As[c4 + 2][row] = v.z;
            As[c4 + 3][row] = v.w;
        }
#pragma unroll
        for (int t = 0; t < 2; t++) {
            int id  = tid + t * 256;
            int row = id >> 4;
            int c4  = (id & 15) << 2;
            *(float4*)(&Bs[row][c4]) = *(const float4*)(Wh + (k0 + row) * DD + c4);
        }
        __syncthreads();

#pragma unroll 8
        for (int kk = 0; kk < 32; kk++) {
            ulonglong2 a01 = *(const ulonglong2*)(&As[kk][tm * 8]);
            ulonglong2 a23 = *(const ulonglong2*)(&As[kk][tm * 8 + 4]);
            float4 b4 = *(const float4*)(&Bs[kk][tn * 4]);
            unsigned long long bd0 = f2pack(b4.x, b4.x);
            unsigned long long bd1 = f2pack(b4.y, b4.y);
            unsigned long long bd2 = f2pack(b4.z, b4.z);
            unsigned long long bd3 = f2pack(b4.w, b4.w);
            ffma2(acc2[0][0], a01.x, bd0); ffma2(acc2[0][1], a01.x, bd1);
            ffma2(acc2[0][2], a01.x, bd2); ffma2(acc2[0][3], a01.x, bd3);
            ffma2(acc2[1][0], a01.y, bd0); ffma2(acc2[1][1], a01.y, bd1);
            ffma2(acc2[1][2], a01.y, bd2); ffma2(acc2[1][3], a01.y, bd3);
            ffma2(acc2[2][0], a23.x, bd0); ffma2(acc2[2][1], a23.x, bd1);
            ffma2(acc2[2][2], a23.x, bd2); ffma2(acc2[2][3], a23.x, bd3);
            ffma2(acc2[3][0], a23.y, bd0); ffma2(acc2[3][1], a23.y, bd1);
            ffma2(acc2[3][2], a23.y, bd2); ffma2(acc2[3][3], a23.y, bd3);
        }
        __syncthreads();
    }

#pragma unroll
    for (int p = 0; p < 4; p++) {
        float lo[4], hi[4];
#pragma unroll
        for (int j = 0; j < 4; j++) f2unpack(acc2[p][j], lo[j], hi[j]);
#pragma unroll
        for (int hlf = 0; hlf < 2; hlf++) {
            int r = r0 + tm * 8 + 2 * p + hlf;
            int b = r >> 10;
            int g = r & (GG - 1);
            float* s = hlf ? hi : lo;
            float4 o4 = make_float4(s[0], s[1], s[2], s[3]);
            *(float4*)(outbuf + (((b * HH + hh) * GG + g) * DD) + tn * 4) = o4;
        }
    }
}

// ---------------------------------------------------------------------------
// Flash attention: one CTA per (b*h, q-tile of 64). 128 threads.
// S-GEMM: FFMA2 pairs along rows (free from d-major Qs); K scalar dup'd.
// PV:     FFMA2 pairs along n-cols (free from natural Vs); P scalar dup'd.
// ---------------------------------------------------------------------------
__global__ __launch_bounds__(128) void attn_kernel(
    const int* __restrict__ mask,
    float* __restrict__ out)
{
    __shared__ float Qs[64 * 64];     // Qs[d*64 + i]
    __shared__ float KP[64 * 64];     // Ks[d*64 + j]  then  Ps[i*64 + j]
    __shared__ float Vs[64 * 64];     // Vs[j*64 + n]

    const int q0 = blockIdx.x * 64;
    const int bh = blockIdx.y;

    const float* qb = g_q + (size_t)bh * GG * DD;
    const float* kb = g_k + (size_t)bh * GG * DD;
    const float* vb = g_v + (size_t)bh * GG * DD;

    const int tid = threadIdx.x;
    const int tm = tid >> 4;          // 0..7  -> rows tm*8..+7
    const int tn = tid & 15;          // 0..15 -> cols tn*4..+3

#pragma unroll
    for (int t = 0; t < 8; t++) {
        int id = tid + t * 128;
        int i  = id >> 4;
        int d4 = (id & 15) << 2;
        float4 v = *(const float4*)(qb + (q0 + i) * DD + d4);
        Qs[(d4 + 0) * 64 + i] = v.x;
        Qs[(d4 + 1) * 64 + i] = v.y;
        Qs[(d4 + 2) * 64 + i] = v.z;
        Qs[(d4 + 3) * 64 + i] = v.w;
    }

    unsigned long long o2[8][2];      // [row][n-pair]: lo=col tn*4+2p, hi=+1
    float m[8], l[8];
#pragma unroll
    for (int ii = 0; ii < 8; ii++) {
        m[ii] = -3.0e38f;
        l[ii] = 0.f;
        o2[ii][0] = 0ull; o2[ii][1] = 0ull;
    }
    const float scale = 0.125f;

    for (int k0 = 0; k0 < GG; k0 += 64) {
        __syncthreads();
#pragma unroll
        for (int t = 0; t < 8; t++) {
            int id = tid + t * 128;
            int j  = id >> 4;
            int d4 = (id & 15) << 2;
            float4 kv = *(const float4*)(kb + (k0 + j) * DD + d4);
            KP[(d4 + 0) * 64 + j] = kv.x;
            KP[(d4 + 1) * 64 + j] = kv.y;
            KP[(d4 + 2) * 64 + j] = kv.z;
            KP[(d4 + 3) * 64 + j] = kv.w;
            *(float4*)(&Vs[j * 64 + d4]) = *(const float4*)(vb + (k0 + j) * DD + d4);
        }
        __syncthreads();

        // S = Q K^T, row-pair packed accumulators
        unsigned long long s2[4][4];
#pragma unroll
        for (int p = 0; p < 4; p++)
#pragma unroll
            for (int j = 0; j < 4; j++) s2[p][j] = 0ull;

#pragma unroll 8
        for (int d = 0; d < 64; d++) {
            ulonglong2 a01 = *(const ulonglong2*)(&Qs[d * 64 + tm * 8]);
            ulonglong2 a23 = *(const ulonglong2*)(&Qs[d * 64 + tm * 8 + 4]);
            float4 b4 = *(const float4*)(&KP[d * 64 + tn * 4]);
            unsigned long long bd0 = f2pack(b4.x, b4.x);
            unsigned long long bd1 = f2pack(b4.y, b4.y);
            unsigned long long bd2 = f2pack(b4.z, b4.z);
            unsigned long long bd3 = f2pack(b4.w, b4.w);
            ffma2(s2[0][0], a01.x, bd0); ffma2(s2[0][1], a01.x, bd1);
            ffma2(s2[0][2], a01.x, bd2); ffma2(s2[0][3], a01.x, bd3);
            ffma2(s2[1][0], a01.y, bd0); ffma2(s2[1][1], a01.y, bd1);
            ffma2(s2[1][2], a01.y, bd2); ffma2(s2[1][3], a01.y, bd3);
            ffma2(s2[2][0], a23.x, bd0); ffma2(s2[2][1], a23.x, bd1);
            ffma2(s2[2][2], a23.x, bd2); ffma2(s2[2][3], a23.x, bd3);
            ffma2(s2[3][0], a23.y, bd0); ffma2(s2[3][1], a23.y, bd1);
            ffma2(s2[3][2], a23.y, bd2); ffma2(s2[3][3], a23.y, bd3);
        }
        __syncthreads();              // done reading K before P overwrite

        // unpack S into per-row scalars
        float s[8][4];
#pragma unroll
        for (int p = 0; p < 4; p++)
#pragma unroll
            for (int j = 0; j < 4; j++)
                f2unpack(s2[p][j], s[2 * p][j], s[2 * p + 1][j]);

        // mask + scale + online softmax
#pragma unroll
        for (int ii = 0; ii < 8; ii++) {
            int qi = q0 + tm * 8 + ii;
            int4 mk = *(const int4*)(mask + qi * GG + k0 + tn * 4);
            s[ii][0] = mk.x ? NEG_INF : s[ii][0] * scale;
            s[ii][1] = mk.y ? NEG_INF : s[ii][1] * scale;
            s[ii][2] = mk.z ? NEG_INF : s[ii][2] * scale;
            s[ii][3] = mk.w ? NEG_INF : s[ii][3] * scale;

            float tmax = fmaxf(fmaxf(s[ii][0], s[ii][1]), fmaxf(s[ii][2], s[ii][3]));
#pragma unroll
            for (int off = 8; off; off >>= 1)
                tmax = fmaxf(tmax, __shfl_xor_sync(0xffffffffu, tmax, off, 16));

            float mn    = fmaxf(m[ii], tmax);
            float alpha = __expf(m[ii] - mn);
            m[ii] = mn;

            float rs = 0.f;
#pragma unroll
            for (int jj = 0; jj < 4; jj++) {
                s[ii][jj] = __expf(s[ii][jj] - mn);
                rs += s[ii][jj];
            }
#pragma unroll
            for (int off = 8; off; off >>= 1)
                rs += __shfl_xor_sync(0xffffffffu, rs, off, 16);

            l[ii] = l[ii] * alpha + rs;
            unsigned long long al = f2pack(alpha, alpha);
            o2[ii][0] = fmul2(o2[ii][0], al);
            o2[ii][1] = fmul2(o2[ii][1], al);

            *(float4*)(&KP[(tm * 8 + ii) * 64 + tn * 4]) =
                make_float4(s[ii][0], s[ii][1], s[ii][2], s[ii][3]);
        }
        __syncthreads();

        // O += P @ V : j chunked by 4, P rows as float4, V n-pairs free
#pragma unroll 2
        for (int j0 = 0; j0 < 64; j0 += 4) {
            float4 p4[8];
#pragma unroll
            for (int ii = 0; ii < 8; ii++)
                p4[ii] = *(const float4*)(&KP[(tm * 8 + ii) * 64 + j0]);
#pragma unroll
            for (int jj = 0; jj < 4; jj++) {
                ulonglong2 bv = *(const ulonglong2*)(&Vs[(j0 + jj) * 64 + tn * 4]);
                const float* pf = (const float*)p4;
#pragma unroll
                for (int ii = 0; ii < 8; ii++) {
                    float pv = pf[ii * 4 + jj];
                    unsigned long long ad = f2pack(pv, pv);
                    ffma2(o2[ii][0], ad, bv.x);
                    ffma2(o2[ii][1], ad, bv.y);
                }
            }
        }
    }

    // epilogue
#pragma unroll
    for (int ii = 0; ii < 8; ii++) {
        float inv = 1.f / l[ii];
        float f0, f1, f2, f3;
        f2unpack(o2[ii][0], f0, f1);
        f2unpack(o2[ii][1], f2, f3);
        float4 o4 = make_float4(f0 * inv, f1 * inv, f2 * inv, f3 * inv);
        *(float4*)(out + ((size_t)bh * GG + q0 + tm * 8 + ii) * DD + tn * 4) = o4;
    }
}

// ---------------------------------------------------------------------------
extern "C" void kernel_launch(void* const* d_in, const int* in_sizes, int n_in,
                              void* d_out, int out_size)
{
    const float* h    = (const float*)d_in[0];
    const int*   mask = (const int*)  d_in[1];
    const float* W_Q  = (const float*)d_in[2];
    const float* W_K  = (const float*)d_in[3];
    const float* W_V  = (const float*)d_in[4];
    float* out = (float*)d_out;

    dim3 pgrid(128, 8);
    proj_kernel<<<pgrid, 256>>>(h, W_Q, 0);
    proj_kernel<<<pgrid, 256>>>(h, W_K, 1);
    proj_kernel<<<pgrid, 256>>>(h, W_V, 2);

    dim3 agrid(GG / 64, BB * HH);
    attn_kernel<<<agrid, 128>>>(mask, out);
}